// round 2
// baseline (speedup 1.0000x reference)
#include <cuda_runtime.h>
#include <cstdint>

#define BATCH       8192
#define FEAT_DIM    2048
#define NUM_CLASSES 751
#define TPB         256

// Scratch (device globals; allocation is forbidden)
__device__ float        g_rowdist[BATCH];
__device__ unsigned int g_done_count;   // zero-initialized at load; last block resets it

// ---------------------------------------------------------------------------
// Single fused kernel: one block per batch row.
//  - per-block label-width micro-detection (odd words of first 64 pairs)
//  - ||x_b - c_{label_b}||^2, clamp to [1e-12, 1e12], store
//  - last finishing block deterministically reduces all 8192 partials,
//    adds the clipped-zero constant, divides by BATCH, writes the scalar,
//    and resets the counter so CUDA-graph replays see identical state.
// ---------------------------------------------------------------------------
__global__ void __launch_bounds__(TPB, 8)
center_loss_fused_kernel(const float* __restrict__ x,
                         const int*   __restrict__ labels_any,
                         const float* __restrict__ centers,
                         float*       __restrict__ out) {
    const int b    = blockIdx.x;
    const int tid  = threadIdx.x;
    const int lane = tid & 31;
    const int wid  = tid >> 5;

    // ---- label-width detection (int64 vs int32), ~free: 256B from L1/L2 ----
    // If int64 LE: words at odd int32 indices are high halves of values in
    // [0,751) -> all zero. If int32 random labels: P(64 consecutive == 0) ~ 0.
    __shared__ int s_nz;
    if (tid == 0) s_nz = 0;
    __syncthreads();
    if (tid < 64 && labels_any[2 * tid + 1] != 0) s_nz = 1;  // monotone race OK
    __syncthreads();
    const bool is_i64 = (s_nz == 0);

    long long lbl = is_i64 ? __ldg(((const long long*)labels_any) + b)
                           : (long long)__ldg(labels_any + b);

    const float4* __restrict__ xr = (const float4*)(x       + (size_t)b   * FEAT_DIM);
    const float4* __restrict__ cr = (const float4*)(centers + (size_t)lbl * FEAT_DIM);

    // ---- squared distance: 512 float4 / 256 threads = 2 each, front-batched ----
    float4 a0 = __ldg(xr + tid);
    float4 a1 = __ldg(xr + tid + TPB);
    float4 c0 = __ldg(cr + tid);
    float4 c1 = __ldg(cr + tid + TPB);

    float d;
    float acc;
    d = a0.x - c0.x; acc  = d * d;
    d = a0.y - c0.y; acc += d * d;
    d = a0.z - c0.z; acc += d * d;
    d = a0.w - c0.w; acc += d * d;
    d = a1.x - c1.x; acc += d * d;
    d = a1.y - c1.y; acc += d * d;
    d = a1.z - c1.z; acc += d * d;
    d = a1.w - c1.w; acc += d * d;

    #pragma unroll
    for (int off = 16; off > 0; off >>= 1)
        acc += __shfl_down_sync(0xFFFFFFFFu, acc, off);

    __shared__ float s_warp[TPB / 32];
    if (lane == 0) s_warp[wid] = acc;
    __syncthreads();

    __shared__ bool s_is_last;
    if (tid == 0) {
        float v = 0.0f;
        #pragma unroll
        for (int w = 0; w < TPB / 32; w++) v += s_warp[w];
        v = fminf(fmaxf(v, 1e-12f), 1e12f);      // clamp exactly as reference
        g_rowdist[b] = v;
        __threadfence();
        unsigned int prev = atomicAdd(&g_done_count, 1u);
        s_is_last = (prev == (unsigned int)(BATCH - 1));
    }
    __syncthreads();

    // ---- last block: deterministic fixed-order reduction of 8192 partials ----
    if (s_is_last) {
        float lacc = 0.0f;
        #pragma unroll
        for (int i = tid; i < BATCH; i += TPB)   // 32 per thread, fixed order
            lacc += g_rowdist[i];

        #pragma unroll
        for (int off = 16; off > 0; off >>= 1)
            lacc += __shfl_down_sync(0xFFFFFFFFu, lacc, off);

        __shared__ float s_fin[TPB / 32];
        if (lane == 0) s_fin[wid] = lacc;
        __syncthreads();

        if (tid == 0) {
            float total = 0.0f;
            #pragma unroll
            for (int w = 0; w < TPB / 32; w++) total += s_fin[w];
            const float clipped_zeros =
                (float)BATCH * (float)(NUM_CLASSES - 1) * 1e-12f;
            out[0] = (total + clipped_zeros) / (float)BATCH;
            g_done_count = 0;                    // reset for next graph replay
        }
    }
}

extern "C" void kernel_launch(void* const* d_in, const int* in_sizes, int n_in,
                              void* d_out, int out_size) {
    const float* x       = (const float*)d_in[0];
    const int*   labels  = (const int*)d_in[1];   // width detected in-kernel
    const float* centers = (const float*)d_in[2];
    float*       out     = (float*)d_out;

    center_loss_fused_kernel<<<BATCH, TPB>>>(x, labels, centers, out);
}

// round 3
// speedup vs baseline: 1.3065x; 1.3065x over previous
#include <cuda_runtime.h>
#include <cstdint>

#define BATCH        8192
#define FEAT_DIM     2048
#define NUM_CLASSES  751
#define TPB          256
#define ROWS_PER_BLK 8                      // one warp per row
#define NBLK         (BATCH / ROWS_PER_BLK) // 1024

// Scratch (device globals; allocation forbidden)
__device__ float        g_partial[NBLK];
__device__ unsigned int g_done_count;       // zero at load; last block resets

__global__ void __launch_bounds__(TPB, 2)
center_loss_kernel(const float* __restrict__ x,
                   const int*   __restrict__ labels_i32,
                   const float* __restrict__ centers,
                   float*       __restrict__ out) {
    const int tid  = threadIdx.x;
    const int lane = tid & 31;
    const int wid  = tid >> 5;
    const int row  = blockIdx.x * ROWS_PER_BLK + wid;

    // ---- barrier-free label-width detection (per warp, no smem, no bar) ----
    // int64 LE: odd int32 words of first 16 pairs are high halves of values
    // in [0,751) -> all zero. int32: P(16 consecutive labels == 0) ~ (1/751)^16.
    int hi = (lane < 16) ? __ldg(labels_i32 + 2 * lane + 1) : 0;
    unsigned nz = __ballot_sync(0xFFFFFFFFu, hi != 0);
    const bool is_i64 = (nz == 0u);

    // low int32 word is the label either way
    const int lbl = __ldg(labels_i32 + (is_i64 ? 2 * row : row));

    const float4* __restrict__ xr = (const float4*)(x       + (size_t)row * FEAT_DIM);
    const float4* __restrict__ cr = (const float4*)(centers + (size_t)lbl * FEAT_DIM);

    // ---- 512 float4 per row / 32 lanes = 16 independent pairs per lane ----
    float acc = 0.0f;
    #pragma unroll
    for (int k = 0; k < 16; k++) {
        float4 a = __ldg(xr + lane + 32 * k);
        float4 c = __ldg(cr + lane + 32 * k);
        float d;
        d = a.x - c.x; acc += d * d;
        d = a.y - c.y; acc += d * d;
        d = a.z - c.z; acc += d * d;
        d = a.w - c.w; acc += d * d;
    }

    // warp reduce -> per-row squared distance
    #pragma unroll
    for (int off = 16; off > 0; off >>= 1)
        acc += __shfl_down_sync(0xFFFFFFFFu, acc, off);

    __shared__ float s_row[ROWS_PER_BLK];
    if (lane == 0)
        s_row[wid] = fminf(fmaxf(acc, 1e-12f), 1e12f);  // clamp as reference
    __syncthreads();

    __shared__ bool s_is_last;
    if (tid == 0) {
        float p = 0.0f;
        #pragma unroll
        for (int w = 0; w < ROWS_PER_BLK; w++) p += s_row[w];  // fixed order
        g_partial[blockIdx.x] = p;
        __threadfence();
        unsigned int prev = atomicAdd(&g_done_count, 1u);
        s_is_last = (prev == (unsigned int)(NBLK - 1));
    }
    __syncthreads();

    // ---- last block: deterministic fixed-order reduction of 1024 partials ----
    if (s_is_last) {
        float lacc = 0.0f;
        #pragma unroll
        for (int i = tid; i < NBLK; i += TPB)   // 4 per thread, fixed order
            lacc += g_partial[i];

        #pragma unroll
        for (int off = 16; off > 0; off >>= 1)
            lacc += __shfl_down_sync(0xFFFFFFFFu, lacc, off);

        __shared__ float s_fin[TPB / 32];
        if (lane == 0) s_fin[wid] = lacc;
        __syncthreads();

        if (tid == 0) {
            float total = 0.0f;
            #pragma unroll
            for (int w = 0; w < TPB / 32; w++) total += s_fin[w];
            const float clipped_zeros =
                (float)BATCH * (float)(NUM_CLASSES - 1) * 1e-12f;
            out[0] = (total + clipped_zeros) / (float)BATCH;
            g_done_count = 0;                    // reset for graph replay
        }
    }
}

extern "C" void kernel_launch(void* const* d_in, const int* in_sizes, int n_in,
                              void* d_out, int out_size) {
    const float* x       = (const float*)d_in[0];
    const int*   labels  = (const int*)d_in[1];   // width detected in-kernel
    const float* centers = (const float*)d_in[2];
    float*       out     = (float*)d_out;

    center_loss_kernel<<<NBLK, TPB>>>(x, labels, centers, out);
}